// round 9
// baseline (speedup 1.0000x reference)
#include <cuda_runtime.h>
#include <cuda_fp16.h>
#include <cstdint>

#define DM    1024
#define DM16  64          // DM / 16 (k16 tiles)
#define MTOT  16384

// ---------------------------------------------------------------------------
// Static scratch, fp16 fragment-major (m16n8k16):
//   A-frag: [M/16][K/16][lane 32][4 u32]  (a0..a3, each half2)
//   g_Wgo : [N/8][K/16][lane 32][g_b0,g_b1,o_b0,o_b1]
//   g_Wup : [N/8][K/32][lane 32][b0_e,b1_e,b0_o,b1_o]  (k16 pairs packed)
// ---------------------------------------------------------------------------
__device__ uint32_t g_xr [(size_t)(MTOT / 16) * DM16 * 128];  // 32 MB
__device__ uint32_t g_h  [(size_t)(MTOT / 16) * DM16 * 128];  // 32 MB
__device__ uint32_t g_Wgo[(size_t)128 * DM16 * 128];          // 4 MB
__device__ uint32_t g_Wup[(size_t)128 * 32 * 128];            // 2 MB

// ---------------------------------------------------------------------------
// helpers
// ---------------------------------------------------------------------------
__device__ __forceinline__ uint32_t smem_u32(const void* p) {
    return (uint32_t)__cvta_generic_to_shared(p);
}
__device__ __forceinline__ void cp16(uint32_t dst, const void* src) {
    asm volatile("cp.async.cg.shared.global [%0], [%1], 16;\n" ::"r"(dst), "l"(src));
}
__device__ __forceinline__ void cp_commit() { asm volatile("cp.async.commit_group;\n"); }
template <int N> __device__ __forceinline__ void cp_wait() {
    asm volatile("cp.async.wait_group %0;\n" ::"n"(N));
}
// pack two fp32 -> half2 (lo = first element, in low 16 bits)
__device__ __forceinline__ uint32_t h2(float lo, float hi) {
    uint32_t r;
    asm("cvt.rn.f16x2.f32 %0, %1, %2;" : "=r"(r) : "f"(hi), "f"(lo));
    return r;
}
__device__ __forceinline__ void mma16(float* c, const uint32_t* a, uint32_t b0,
                                      uint32_t b1) {
    asm volatile(
        "mma.sync.aligned.m16n8k16.row.col.f32.f16.f16.f32 "
        "{%0,%1,%2,%3}, {%4,%5,%6,%7}, {%8,%9}, {%0,%1,%2,%3};\n"
        : "+f"(c[0]), "+f"(c[1]), "+f"(c[2]), "+f"(c[3])
        : "r"(a[0]), "r"(a[1]), "r"(a[2]), "r"(a[3]), "r"(b0), "r"(b1));
}

// ---------------------------------------------------------------------------
// Unified pre-pass (ONE launch):
//   bid [0, 8192)       : x -> fp16 A-frag (tile 32 rows x 64 cols)
//   bid [8192, 9216)    : Wg -> g_Wgo[.,0:2]
//   bid [9216, 10240)   : Wo -> g_Wgo[.,2:4]
//   bid [10240, 11264)  : W_out -> g_Wup (k16-pair packed)
// ---------------------------------------------------------------------------
__global__ __launch_bounds__(256) void prepass(const float* __restrict__ x,
                                               const float* __restrict__ Wp,
                                               const float* __restrict__ Wout) {
    __shared__ float T[32][65];
    const int tid = threadIdx.x;
    const int bid = blockIdx.x;

    if (bid < 8192) {
        // ---- x tile: 32 rows x 64 cols ----
        const int c0 = (bid & 15) * 64, r0 = (bid >> 4) * 32;
#pragma unroll
        for (int i = 0; i < 8; ++i) {
            const int lin = i * 256 + tid;
            const int r = lin >> 6, c = lin & 63;
            T[r][c] = x[(size_t)(r0 + r) * DM + c0 + c];
        }
        __syncthreads();
        const int tl = tid >> 5, l = tid & 31;
        const int mtl = tl >> 2, ktl = tl & 3;
        const int r = mtl * 16 + (l >> 2), c = ktl * 16 + (l & 3) * 2;
        uint4 v;
        v.x = h2(T[r][c],         T[r][c + 1]);
        v.y = h2(T[r + 8][c],     T[r + 8][c + 1]);
        v.z = h2(T[r][c + 8],     T[r][c + 9]);
        v.w = h2(T[r + 8][c + 8], T[r + 8][c + 9]);
        const size_t off =
            ((size_t)((bid >> 4) * 2 + mtl) * DM16 + (bid & 15) * 4 + ktl) * 128 +
            l * 4;
        *reinterpret_cast<uint4*>(g_xr + off) = v;
    } else {
        // ---- weight tile: 32 n x 32 k ----
        const int id2 = bid - 8192;
        const int which = id2 >> 10;             // 0: Wg, 1: Wo, 2: W_out
        const int tt = id2 & 1023;
        const int bx = tt & 31, by = tt >> 5;
        const int n0 = bx * 32, k0 = by * 32;
        const float* src = (which == 2) ? Wout : Wp;
        const int srcCols = (which == 2) ? 1024 : 3072;
        const int colOff = (which == 1) ? 2048 : 0;
#pragma unroll
        for (int i = 0; i < 4; ++i) {
            const int lin = i * 256 + tid;
            const int k = lin >> 5, n = lin & 31;
            T[k][n] = src[(size_t)(k0 + k) * srcCols + colOff + n0 + n];
        }
        __syncthreads();
        const int tl = tid >> 5, l = tid & 31;
        const int nbl = tl >> 1, ktl = tl & 1;
        const int n = nbl * 8 + (l >> 2), kk = ktl * 16 + (l & 3) * 2;
        uint2 v;
        v.x = h2(T[kk][n],     T[kk + 1][n]);
        v.y = h2(T[kk + 8][n], T[kk + 9][n]);
        const int nbg = bx * 4 + nbl, ktg = by * 2 + ktl;
        if (which < 2) {
            const size_t off = ((size_t)nbg * DM16 + ktg) * 128 + l * 4 + which * 2;
            *reinterpret_cast<uint2*>(g_Wgo + off) = v;
        } else {
            const size_t off =
                ((size_t)nbg * 32 + (ktg >> 1)) * 128 + l * 4 + (ktg & 1) * 2;
            *reinterpret_cast<uint2*>(g_Wup + off) = v;
        }
    }
}

// ---------------------------------------------------------------------------
// gate smem: 3 stages x 32KB (A 16KB, B 16KB), bias @ 98304.
// out  smem: 3 stages x 24KB (A 16KB, B 8KB),  bias @ 73728.
// ---------------------------------------------------------------------------
#define GSTAGE_B 32768
#define GATE_SMEM (3 * GSTAGE_B + 1024)   // 99328
#define OSTAGE_B 24576
#define OUT_SMEM (3 * OSTAGE_B + 512)     // 74240

// ---------------------------------------------------------------------------
// Kernel 1: G = x@Wg, O = x@Wo, h = (G+bg)*sigmoid(O+bo) -> g_h (fp16 A-frag)
// BM=128 BN=64 BK=64, 16 iters. 8 warps = 4(M) x 2(N), warp tile 32x32.
// ---------------------------------------------------------------------------
__global__ __launch_bounds__(256, 2) void gate_gemm(const float* __restrict__ bp) {
    extern __shared__ __align__(16) char smem[];
    const uint32_t sb = smem_u32(smem);
    const int t = threadIdx.x, lane = t & 31, w = t >> 5;
    const int wm = w & 3, wn = w >> 2;
    const int n0 = blockIdx.x * 64, m0 = blockIdx.y * 128;

    float* bias = reinterpret_cast<float*>(smem + 3 * GSTAGE_B);
    if (t < 64) { bias[t] = bp[n0 + t]; bias[64 + t] = bp[2048 + n0 + t]; }

    float accG[2][4][4] = {};
    float accO[2][4][4] = {};

    auto load_stage = [&](int it) {
        const int s = it % 3;
        const uint32_t* as = g_xr + ((size_t)(m0 / 16 + w) * DM16 + it * 4) * 128;
        const uint32_t* bs = g_Wgo + ((size_t)(n0 / 8 + w) * DM16 + it * 4) * 128;
        const uint32_t ab = sb + s * GSTAGE_B + w * 2048;
        const uint32_t bb = sb + s * GSTAGE_B + 16384 + w * 2048;
#pragma unroll
        for (int k = 0; k < 4; ++k) {
            cp16(ab + k * 512 + lane * 16, as + k * 128 + lane * 4);
            cp16(bb + k * 512 + lane * 16, bs + k * 128 + lane * 4);
        }
        cp_commit();
    };

    load_stage(0);
    load_stage(1);

    for (int it = 0; it < 16; ++it) {
        if (it + 1 < 16) cp_wait<1>(); else cp_wait<0>();
        __syncthreads();
        if (it + 2 < 16) load_stage(it + 2);
        const int s = it % 3;
        const char* A = smem + s * GSTAGE_B;
        const char* B = smem + s * GSTAGE_B + 16384;
#pragma unroll
        for (int kt = 0; kt < 4; ++kt) {
            uint4 av[2], bv[4];
#pragma unroll
            for (int mf = 0; mf < 2; ++mf)
                av[mf] = *reinterpret_cast<const uint4*>(
                    A + (((wm * 2 + mf) * 4 + kt) * 32 + lane) * 16);
#pragma unroll
            for (int nf = 0; nf < 4; ++nf)
                bv[nf] = *reinterpret_cast<const uint4*>(
                    B + (((wn * 4 + nf) * 4 + kt) * 32 + lane) * 16);
#pragma unroll
            for (int mf = 0; mf < 2; ++mf)
#pragma unroll
                for (int nf = 0; nf < 4; ++nf) {
                    mma16(accG[mf][nf], &av[mf].x, bv[nf].x, bv[nf].y);
                    mma16(accO[mf][nf], &av[mf].x, bv[nf].z, bv[nf].w);
                }
        }
    }

    __syncthreads();  // epilogue staging reuses stage smem

    // h = (G+bg)*sigmoid(O+bo) -> packed half2 -> A-frag gather -> g_h
    uint32_t* hb = reinterpret_cast<uint32_t*>(smem) + w * 640;  // 32 x 20 u32
#pragma unroll
    for (int mf = 0; mf < 2; ++mf)
#pragma unroll
        for (int nf = 0; nf < 4; ++nf)
#pragma unroll
            for (int rr = 0; rr < 2; ++rr) {
                const int row = mf * 16 + rr * 8 + (lane >> 2);
                const int col2 = nf * 4 + (lane & 3);
                const float g0 = accG[mf][nf][rr * 2]     + bias[wn * 32 + col2 * 2];
                const float g1 = accG[mf][nf][rr * 2 + 1] + bias[wn * 32 + col2 * 2 + 1];
                const float o0 = accO[mf][nf][rr * 2]     + bias[64 + wn * 32 + col2 * 2];
                const float o1 = accO[mf][nf][rr * 2 + 1] + bias[64 + wn * 32 + col2 * 2 + 1];
                const float h0 = g0 * (1.0f / (1.0f + __expf(-o0)));
                const float h1 = g1 * (1.0f / (1.0f + __expf(-o1)));
                hb[row * 20 + col2] = h2(h0, h1);
            }
    __syncwarp();
#pragma unroll
    for (int mtl = 0; mtl < 2; ++mtl)
#pragma unroll
        for (int ktl = 0; ktl < 2; ++ktl) {
            const int r = mtl * 16 + (lane >> 2), c2 = ktl * 8 + (lane & 3);
            uint4 v;
            v.x = hb[r * 20 + c2];
            v.y = hb[(r + 8) * 20 + c2];
            v.z = hb[r * 20 + c2 + 4];
            v.w = hb[(r + 8) * 20 + c2 + 4];
            const size_t off =
                ((size_t)(m0 / 16 + wm * 2 + mtl) * DM16 + n0 / 16 + wn * 2 + ktl) *
                    128 + lane * 4;
            *reinterpret_cast<uint4*>(g_h + off) = v;
        }
}

// ---------------------------------------------------------------------------
// Kernel 2: out = h @ W_out + b_out.  BM=128 BN=64 BK=64, 16 iters.
// Grid 2048 CTAs (98.8% wave utilization). 8 warps = 4(M) x 2(N), tile 32x32.
// ---------------------------------------------------------------------------
__global__ __launch_bounds__(256, 2) void out_gemm(const float* __restrict__ bout,
                                                   float* __restrict__ out) {
    extern __shared__ __align__(16) char smem[];
    const uint32_t sb = smem_u32(smem);
    const int t = threadIdx.x, lane = t & 31, w = t >> 5;
    const int wm = w & 3, wn = w >> 2;
    const int n0 = blockIdx.x * 64, m0 = blockIdx.y * 128;

    float* bias = reinterpret_cast<float*>(smem + 3 * OSTAGE_B);
    if (t < 64) bias[t] = bout[n0 + t];

    float acc[2][4][4] = {};

    auto load_stage = [&](int it) {
        const int s = it % 3;
        const uint32_t* as = g_h + ((size_t)(m0 / 16 + w) * DM16 + it * 4) * 128;
        const uint32_t ab = sb + s * OSTAGE_B + w * 2048;
#pragma unroll
        for (int k = 0; k < 4; ++k)
            cp16(ab + k * 512 + lane * 16, as + k * 128 + lane * 4);
        // B: 8 nb x 2 ktp x 32 lanes x 16B = 8KB; 2 cp16 per thread
#pragma unroll
        for (int i = 0; i < 2; ++i) {
            const int lin = i * 256 + t;
            const int nb = lin >> 6, rem = lin & 63;
            const int ktp = rem >> 5, l2 = rem & 31;
            cp16(sb + s * OSTAGE_B + 16384 + lin * 16,
                 g_Wup + ((size_t)(n0 / 8 + nb) * 32 + it * 2 + ktp) * 128 + l2 * 4);
        }
        cp_commit();
    };

    load_stage(0);
    load_stage(1);

    for (int it = 0; it < 16; ++it) {
        if (it + 1 < 16) cp_wait<1>(); else cp_wait<0>();
        __syncthreads();
        if (it + 2 < 16) load_stage(it + 2);
        const int s = it % 3;
        const char* A = smem + s * OSTAGE_B;
        const char* B = smem + s * OSTAGE_B + 16384;
#pragma unroll
        for (int ktp = 0; ktp < 2; ++ktp) {
            uint4 bv[4];
#pragma unroll
            for (int nf = 0; nf < 4; ++nf)
                bv[nf] = *reinterpret_cast<const uint4*>(
                    B + (((wn * 4 + nf) * 2 + ktp) * 32 + lane) * 16);
#pragma unroll
            for (int kts = 0; kts < 2; ++kts) {
                const int kt = ktp * 2 + kts;
                uint4 av[2];
#pragma unroll
                for (int mf = 0; mf < 2; ++mf)
                    av[mf] = *reinterpret_cast<const uint4*>(
                        A + (((wm * 2 + mf) * 4 + kt) * 32 + lane) * 16);
#pragma unroll
                for (int mf = 0; mf < 2; ++mf)
#pragma unroll
                    for (int nf = 0; nf < 4; ++nf)
                        mma16(acc[mf][nf], &av[mf].x,
                              kts ? bv[nf].z : bv[nf].x,
                              kts ? bv[nf].w : bv[nf].y);
            }
        }
    }

    __syncthreads();  // epilogue staging reuses stage smem

    // +bias, coalesced fp32 row-major store via smem (warp tile 32x32)
    float* hb = reinterpret_cast<float*>(smem) + w * 1152;  // 32 x 36 floats
#pragma unroll
    for (int mf = 0; mf < 2; ++mf)
#pragma unroll
        for (int nf = 0; nf < 4; ++nf)
#pragma unroll
            for (int rr = 0; rr < 2; ++rr)
#pragma unroll
                for (int j = 0; j < 2; ++j) {
                    const int row = mf * 16 + rr * 8 + (lane >> 2);
                    const int col = nf * 8 + 2 * (lane & 3) + j;
                    hb[row * 36 + col] = acc[mf][nf][rr * 2 + j] +
                                         bias[wn * 32 + col];
                }
    __syncwarp();
#pragma unroll
    for (int i = 0; i < 8; ++i) {
        const int r = i * 4 + (lane >> 3), c4 = lane & 7;
        const float4 v = *reinterpret_cast<const float4*>(hb + r * 36 + c4 * 4);
        *reinterpret_cast<float4*>(
            &out[(size_t)(m0 + wm * 32 + r) * DM + n0 + wn * 32 + c4 * 4]) = v;
    }
}

// ---------------------------------------------------------------------------
// Inputs (metadata order): x, W_proj, b_proj, W_out, b_out, layer_idx, num_layers
// ---------------------------------------------------------------------------
extern "C" void kernel_launch(void* const* d_in, const int* in_sizes, int n_in,
                              void* d_out, int out_size)
{
    const float* x    = (const float*)d_in[0];
    const float* Wp   = (const float*)d_in[1];
    const float* bp   = (const float*)d_in[2];
    const float* Wout = (const float*)d_in[3];
    const float* bout = (const float*)d_in[4];
    float* out = (float*)d_out;

    cudaFuncSetAttribute(gate_gemm, cudaFuncAttributeMaxDynamicSharedMemorySize,
                         GATE_SMEM);
    cudaFuncSetAttribute(out_gemm, cudaFuncAttributeMaxDynamicSharedMemorySize,
                         OUT_SMEM);

    prepass<<<11264, 256>>>(x, Wp, Wout);   // one launch: x + all 3 weight slabs

    gate_gemm<<<dim3(16, 128), 256, GATE_SMEM>>>(bp);
    out_gemm <<<dim3(16, 128), 256, OUT_SMEM>>>(bout, out);
}

// round 10
// speedup vs baseline: 1.0656x; 1.0656x over previous
#include <cuda_runtime.h>
#include <cuda_fp16.h>
#include <cstdint>

#define DM    1024
#define DM16  64          // DM / 16 (k16 tiles)
#define MTOT  16384

// ---------------------------------------------------------------------------
// Static scratch, fp16 fragment-major (m16n8k16):
//   A-frag: [M/16][K/16][lane 32][4 u32]  (a0..a3, each half2)
//   g_Wgo : [N/8][K/16][lane 32][g_b0,g_b1,o_b0,o_b1]
//   g_Wup : [N/8][K/32][lane 32][b0_e,b1_e,b0_o,b1_o]  (k16 pairs packed)
// ---------------------------------------------------------------------------
__device__ uint32_t g_xr [(size_t)(MTOT / 16) * DM16 * 128];  // 32 MB
__device__ uint32_t g_h  [(size_t)(MTOT / 16) * DM16 * 128];  // 32 MB
__device__ uint32_t g_Wgo[(size_t)128 * DM16 * 128];          // 4 MB
__device__ uint32_t g_Wup[(size_t)128 * 32 * 128];            // 2 MB

// ---------------------------------------------------------------------------
// helpers
// ---------------------------------------------------------------------------
__device__ __forceinline__ uint32_t smem_u32(const void* p) {
    return (uint32_t)__cvta_generic_to_shared(p);
}
__device__ __forceinline__ void cp16(uint32_t dst, const void* src) {
    asm volatile("cp.async.cg.shared.global [%0], [%1], 16;\n" ::"r"(dst), "l"(src));
}
__device__ __forceinline__ void cp_commit() { asm volatile("cp.async.commit_group;\n"); }
template <int N> __device__ __forceinline__ void cp_wait() {
    asm volatile("cp.async.wait_group %0;\n" ::"n"(N));
}
// pack two fp32 -> half2 (lo = first element, in low 16 bits)
__device__ __forceinline__ uint32_t h2(float lo, float hi) {
    uint32_t r;
    asm("cvt.rn.f16x2.f32 %0, %1, %2;" : "=r"(r) : "f"(hi), "f"(lo));
    return r;
}
__device__ __forceinline__ void mma16(float* c, const uint32_t* a, uint32_t b0,
                                      uint32_t b1) {
    asm volatile(
        "mma.sync.aligned.m16n8k16.row.col.f32.f16.f16.f32 "
        "{%0,%1,%2,%3}, {%4,%5,%6,%7}, {%8,%9}, {%0,%1,%2,%3};\n"
        : "+f"(c[0]), "+f"(c[1]), "+f"(c[2]), "+f"(c[3])
        : "r"(a[0]), "r"(a[1]), "r"(a[2]), "r"(a[3]), "r"(b0), "r"(b1));
}

// ---------------------------------------------------------------------------
// Unified pre-pass (ONE launch), vectorized LDG.128/STS.128:
//   bid [0, 8192)       : x -> fp16 A-frag (tile 32 rows x 64 cols)
//   bid [8192, 9216)    : Wg -> g_Wgo[.,0:2]
//   bid [9216, 10240)   : Wo -> g_Wgo[.,2:4]
//   bid [10240, 11264)  : W_out -> g_Wup (k16-pair packed)
// Smem pitch 68 floats: keeps float4 stores 16B-aligned for every row.
// ---------------------------------------------------------------------------
__global__ __launch_bounds__(256) void prepass(const float* __restrict__ x,
                                               const float* __restrict__ Wp,
                                               const float* __restrict__ Wout) {
    __shared__ float T[32][68];
    const int tid = threadIdx.x;
    const int bid = blockIdx.x;

    if (bid < 8192) {
        // ---- x tile: 32 rows x 64 cols, 2 float4 loads/thread ----
        const int c0 = (bid & 15) * 64, r0 = (bid >> 4) * 32;
#pragma unroll
        for (int i = 0; i < 2; ++i) {
            const int lin = i * 256 + tid;          // 0..511
            const int r = lin >> 4, c4 = (lin & 15) << 2;
            const float4 v = *reinterpret_cast<const float4*>(
                x + (size_t)(r0 + r) * DM + c0 + c4);
            *reinterpret_cast<float4*>(&T[r][c4]) = v;
        }
        __syncthreads();
        const int tl = tid >> 5, l = tid & 31;
        const int mtl = tl >> 2, ktl = tl & 3;
        const int r = mtl * 16 + (l >> 2), c = ktl * 16 + (l & 3) * 2;
        uint4 v;
        v.x = h2(T[r][c],         T[r][c + 1]);
        v.y = h2(T[r + 8][c],     T[r + 8][c + 1]);
        v.z = h2(T[r][c + 8],     T[r][c + 9]);
        v.w = h2(T[r + 8][c + 8], T[r + 8][c + 9]);
        const size_t off =
            ((size_t)((bid >> 4) * 2 + mtl) * DM16 + (bid & 15) * 4 + ktl) * 128 +
            l * 4;
        *reinterpret_cast<uint4*>(g_xr + off) = v;
    } else {
        // ---- weight tile: 32 k x 32 n, 1 float4 load/thread ----
        const int id2 = bid - 8192;
        const int which = id2 >> 10;             // 0: Wg, 1: Wo, 2: W_out
        const int tt = id2 & 1023;
        const int bx = tt & 31, by = tt >> 5;
        const int n0 = bx * 32, k0 = by * 32;
        const float* src = (which == 2) ? Wout : Wp;
        const int srcCols = (which == 2) ? 1024 : 3072;
        const int colOff = (which == 1) ? 2048 : 0;
        {
            const int k = tid >> 3, c4 = (tid & 7) << 2;
            const float4 v = *reinterpret_cast<const float4*>(
                src + (size_t)(k0 + k) * srcCols + colOff + n0 + c4);
            *reinterpret_cast<float4*>(&T[k][c4]) = v;   // T[k][n]
        }
        __syncthreads();
        const int tl = tid >> 5, l = tid & 31;
        const int nbl = tl >> 1, ktl = tl & 1;
        const int n = nbl * 8 + (l >> 2), kk = ktl * 16 + (l & 3) * 2;
        uint2 v;
        v.x = h2(T[kk][n],     T[kk + 1][n]);
        v.y = h2(T[kk + 8][n], T[kk + 9][n]);
        const int nbg = bx * 4 + nbl, ktg = by * 2 + ktl;
        if (which < 2) {
            const size_t off = ((size_t)nbg * DM16 + ktg) * 128 + l * 4 + which * 2;
            *reinterpret_cast<uint2*>(g_Wgo + off) = v;
        } else {
            const size_t off =
                ((size_t)nbg * 32 + (ktg >> 1)) * 128 + l * 4 + (ktg & 1) * 2;
            *reinterpret_cast<uint2*>(g_Wup + off) = v;
        }
    }
}

// ---------------------------------------------------------------------------
// Smem: 3 stages x 32KB (A 16KB, B 16KB), bias @ 98304.
// ---------------------------------------------------------------------------
#define STAGE_B 32768
#define SMEM_BYTES (3 * STAGE_B + 1024)   // 99328

// ---------------------------------------------------------------------------
// Kernel 1: G = x@Wg, O = x@Wo, h = (G+bg)*sigmoid(O+bo) -> g_h (fp16 A-frag)
// BM=128 BN=64 BK=64, 16 iters. 8 warps = 4(M) x 2(N), warp tile 32x32.
// ---------------------------------------------------------------------------
__global__ __launch_bounds__(256, 2) void gate_gemm(const float* __restrict__ bp) {
    extern __shared__ __align__(16) char smem[];
    const uint32_t sb = smem_u32(smem);
    const int t = threadIdx.x, lane = t & 31, w = t >> 5;
    const int wm = w & 3, wn = w >> 2;
    const int n0 = blockIdx.x * 64, m0 = blockIdx.y * 128;

    float* bias = reinterpret_cast<float*>(smem + 3 * STAGE_B);
    if (t < 64) { bias[t] = bp[n0 + t]; bias[64 + t] = bp[2048 + n0 + t]; }

    float accG[2][4][4] = {};
    float accO[2][4][4] = {};

    auto load_stage = [&](int it) {
        const int s = it % 3;
        const uint32_t* as = g_xr + ((size_t)(m0 / 16 + w) * DM16 + it * 4) * 128;
        const uint32_t* bs = g_Wgo + ((size_t)(n0 / 8 + w) * DM16 + it * 4) * 128;
        const uint32_t ab = sb + s * STAGE_B + w * 2048;
        const uint32_t bb = sb + s * STAGE_B + 16384 + w * 2048;
#pragma unroll
        for (int k = 0; k < 4; ++k) {
            cp16(ab + k * 512 + lane * 16, as + k * 128 + lane * 4);
            cp16(bb + k * 512 + lane * 16, bs + k * 128 + lane * 4);
        }
        cp_commit();
    };

    load_stage(0);
    load_stage(1);

    for (int it = 0; it < 16; ++it) {
        if (it + 1 < 16) cp_wait<1>(); else cp_wait<0>();
        __syncthreads();
        if (it + 2 < 16) load_stage(it + 2);
        const int s = it % 3;
        const char* A = smem + s * STAGE_B;
        const char* B = smem + s * STAGE_B + 16384;
#pragma unroll
        for (int kt = 0; kt < 4; ++kt) {
            uint4 av[2], bv[4];
#pragma unroll
            for (int mf = 0; mf < 2; ++mf)
                av[mf] = *reinterpret_cast<const uint4*>(
                    A + (((wm * 2 + mf) * 4 + kt) * 32 + lane) * 16);
#pragma unroll
            for (int nf = 0; nf < 4; ++nf)
                bv[nf] = *reinterpret_cast<const uint4*>(
                    B + (((wn * 4 + nf) * 4 + kt) * 32 + lane) * 16);
#pragma unroll
            for (int mf = 0; mf < 2; ++mf)
#pragma unroll
                for (int nf = 0; nf < 4; ++nf) {
                    mma16(accG[mf][nf], &av[mf].x, bv[nf].x, bv[nf].y);
                    mma16(accO[mf][nf], &av[mf].x, bv[nf].z, bv[nf].w);
                }
        }
    }

    __syncthreads();  // epilogue staging reuses stage smem

    // h = (G+bg)*sigmoid(O+bo) -> packed half2 -> A-frag gather -> g_h
    uint32_t* hb = reinterpret_cast<uint32_t*>(smem) + w * 640;  // 32 x 20 u32
#pragma unroll
    for (int mf = 0; mf < 2; ++mf)
#pragma unroll
        for (int nf = 0; nf < 4; ++nf)
#pragma unroll
            for (int rr = 0; rr < 2; ++rr) {
                const int row = mf * 16 + rr * 8 + (lane >> 2);
                const int col2 = nf * 4 + (lane & 3);
                const float g0 = accG[mf][nf][rr * 2]     + bias[wn * 32 + col2 * 2];
                const float g1 = accG[mf][nf][rr * 2 + 1] + bias[wn * 32 + col2 * 2 + 1];
                const float o0 = accO[mf][nf][rr * 2]     + bias[64 + wn * 32 + col2 * 2];
                const float o1 = accO[mf][nf][rr * 2 + 1] + bias[64 + wn * 32 + col2 * 2 + 1];
                const float h0 = g0 * (1.0f / (1.0f + __expf(-o0)));
                const float h1 = g1 * (1.0f / (1.0f + __expf(-o1)));
                hb[row * 20 + col2] = h2(h0, h1);
            }
    __syncwarp();
#pragma unroll
    for (int mtl = 0; mtl < 2; ++mtl)
#pragma unroll
        for (int ktl = 0; ktl < 2; ++ktl) {
            const int r = mtl * 16 + (lane >> 2), c2 = ktl * 8 + (lane & 3);
            uint4 v;
            v.x = hb[r * 20 + c2];
            v.y = hb[(r + 8) * 20 + c2];
            v.z = hb[r * 20 + c2 + 4];
            v.w = hb[(r + 8) * 20 + c2 + 4];
            const size_t off =
                ((size_t)(m0 / 16 + wm * 2 + mtl) * DM16 + n0 / 16 + wn * 2 + ktl) *
                    128 + lane * 4;
            *reinterpret_cast<uint4*>(g_h + off) = v;
        }
}

// ---------------------------------------------------------------------------
// Kernel 2: out = h @ W_out + b_out.  BM=128 BN=128 BK=64, 16 iters.
// 8 warps = 2(M) x 4(N), warp tile 64x32.  (R7 configuration)
// ---------------------------------------------------------------------------
__global__ __launch_bounds__(256, 2) void out_gemm(const float* __restrict__ bout,
                                                   float* __restrict__ out) {
    extern __shared__ __align__(16) char smem[];
    const uint32_t sb = smem_u32(smem);
    const int t = threadIdx.x, lane = t & 31, w = t >> 5;
    const int wm = w & 1, wn = w >> 1;
    const int n0 = blockIdx.x * 128, m0 = blockIdx.y * 128;

    float* bias = reinterpret_cast<float*>(smem + 3 * STAGE_B);
    if (t < 128) bias[t] = bout[n0 + t];

    float acc[4][4][4] = {};

    auto load_stage = [&](int it) {
        const int s = it % 3;
        const uint32_t* as = g_h + ((size_t)(m0 / 16 + w) * DM16 + it * 4) * 128;
        const uint32_t ab = sb + s * STAGE_B + w * 2048;
#pragma unroll
        for (int k = 0; k < 4; ++k)
            cp16(ab + k * 512 + lane * 16, as + k * 128 + lane * 4);
#pragma unroll
        for (int i = 0; i < 4; ++i) {
            const int lin = i * 256 + t;
            const int nb = lin >> 6, rem = lin & 63;
            const int ktp = rem >> 5, l2 = rem & 31;
            cp16(sb + s * STAGE_B + 16384 + lin * 16,
                 g_Wup + ((size_t)(n0 / 8 + nb) * 32 + it * 2 + ktp) * 128 + l2 * 4);
        }
        cp_commit();
    };

    load_stage(0);
    load_stage(1);

    for (int it = 0; it < 16; ++it) {
        if (it + 1 < 16) cp_wait<1>(); else cp_wait<0>();
        __syncthreads();
        if (it + 2 < 16) load_stage(it + 2);
        const int s = it % 3;
        const char* A = smem + s * STAGE_B;
        const char* B = smem + s * STAGE_B + 16384;
#pragma unroll
        for (int ktp = 0; ktp < 2; ++ktp) {
            uint4 bv[4];
#pragma unroll
            for (int nf = 0; nf < 4; ++nf)
                bv[nf] = *reinterpret_cast<const uint4*>(
                    B + (((wn * 4 + nf) * 2 + ktp) * 32 + lane) * 16);
#pragma unroll
            for (int kts = 0; kts < 2; ++kts) {
                const int kt = ktp * 2 + kts;
                uint4 av[4];
#pragma unroll
                for (int mf = 0; mf < 4; ++mf)
                    av[mf] = *reinterpret_cast<const uint4*>(
                        A + (((wm * 4 + mf) * 4 + kt) * 32 + lane) * 16);
#pragma unroll
                for (int mf = 0; mf < 4; ++mf)
#pragma unroll
                    for (int nf = 0; nf < 4; ++nf)
                        mma16(acc[mf][nf], &av[mf].x,
                              kts ? bv[nf].z : bv[nf].x,
                              kts ? bv[nf].w : bv[nf].y);
            }
        }
    }

    __syncthreads();  // epilogue staging reuses stage smem

    // +bias, coalesced fp32 row-major store via smem
    float* hb = reinterpret_cast<float*>(smem) + w * 1152;  // 32 x 36 floats
#pragma unroll
    for (int ch = 0; ch < 2; ++ch) {
#pragma unroll
        for (int mfl = 0; mfl < 2; ++mfl)
#pragma unroll
            for (int nf = 0; nf < 4; ++nf)
#pragma unroll
                for (int rr = 0; rr < 2; ++rr)
#pragma unroll
                    for (int j = 0; j < 2; ++j) {
                        const int row = mfl * 16 + rr * 8 + (lane >> 2);
                        const int col = nf * 8 + 2 * (lane & 3) + j;
                        hb[row * 36 + col] = acc[ch * 2 + mfl][nf][rr * 2 + j] +
                                             bias[wn * 32 + col];
                    }
        __syncwarp();
#pragma unroll
        for (int i = 0; i < 8; ++i) {
            const int r = i * 4 + (lane >> 3), c4 = lane & 7;
            const float4 v = *reinterpret_cast<const float4*>(hb + r * 36 + c4 * 4);
            *reinterpret_cast<float4*>(
                &out[(size_t)(m0 + wm * 64 + ch * 32 + r) * DM + n0 + wn * 32 +
                     c4 * 4]) = v;
        }
        __syncwarp();
    }
}

// ---------------------------------------------------------------------------
// Inputs (metadata order): x, W_proj, b_proj, W_out, b_out, layer_idx, num_layers
// ---------------------------------------------------------------------------
extern "C" void kernel_launch(void* const* d_in, const int* in_sizes, int n_in,
                              void* d_out, int out_size)
{
    const float* x    = (const float*)d_in[0];
    const float* Wp   = (const float*)d_in[1];
    const float* bp   = (const float*)d_in[2];
    const float* Wout = (const float*)d_in[3];
    const float* bout = (const float*)d_in[4];
    float* out = (float*)d_out;

    cudaFuncSetAttribute(gate_gemm, cudaFuncAttributeMaxDynamicSharedMemorySize,
                         SMEM_BYTES);
    cudaFuncSetAttribute(out_gemm, cudaFuncAttributeMaxDynamicSharedMemorySize,
                         SMEM_BYTES);

    prepass<<<11264, 256>>>(x, Wp, Wout);   // one launch: x + all 3 weight slabs

    gate_gemm<<<dim3(16, 128), 256, SMEM_BYTES>>>(bp);
    out_gemm <<<dim3(8, 128),  256, SMEM_BYTES>>>(bout, out);
}